// round 15
// baseline (speedup 1.0000x reference)
#include <cuda_runtime.h>
#include <cuda_fp16.h>
#include <cstdint>

#define NNODES 50000
#define NEDGES 800000
#define NGRAPHS 64
#define NEG_SLOPE 0.2f

// ---------------- scratch (static __device__, 16B aligned, no allocation) ---
__device__ __align__(16) __half2 g_xh[(size_t)NNODES * 64];   // x (fp16)
__device__ __align__(16) __half2 g_hh[(size_t)NNODES * 64];   // h (fp16) for gathers
__device__ __align__(16) __half2 g_bufA[(size_t)NNODES * 64]; // layer outputs (fp16)
__device__ __align__(16) __half2 g_bufB[(size_t)NNODES * 64];
__device__ __align__(16) __half g_Wh0[128 * 128];
__device__ __align__(16) __half g_Wh1[128 * 128];
__device__ __align__(16) __half g_Wh2[128 * 64];
__device__ __align__(16) float g_as[NNODES];
__device__ __align__(16) float g_ad[NNODES];
__device__ __align__(16) int g_cnt[NNODES];    // zero at entry; scan resets it
__device__ __align__(16) int g_off[NNODES + 1];
__device__ __align__(16) int g_cur[NNODES];
__device__ __align__(16) int g_esrc[NEDGES];
__device__ __align__(16) int g_src[NEDGES];
__device__ __align__(16) int g_dst[NEDGES];
__device__ __align__(16) int g_batch[NNODES];

__device__ __forceinline__ float lrelu(float x) { return x > 0.f ? x : NEG_SLOPE * x; }
__device__ __forceinline__ int clampi(int v, int lo, int hi) {
    return v < lo ? lo : (v > hi ? hi : v);
}

__device__ __forceinline__ const __half2* sel_in(int i) {
    if (i == 1) return g_bufA;
    if (i == 2) return g_bufB;
    return g_xh;
}
__device__ __forceinline__ __half2* sel_out(int i) {
    if (i == 2) return g_bufB;
    return g_bufA;
}

// int64 little-endian probe: high dword of each elem is 0
__device__ __forceinline__ int probe_is64(const int* ei32) {
    int acc = 0;
#pragma unroll
    for (int i = 1; i < 64; i += 2) acc |= __ldg(&ei32[i]);
    return acc == 0;
}

// ---------------- fp16 mma m16n8k16 + ldmatrix + cp.async ----------------
__device__ __forceinline__ void mma_f16(float* d, const uint32_t* a, const uint32_t* b) {
    asm volatile(
        "mma.sync.aligned.m16n8k16.row.col.f32.f16.f16.f32 "
        "{%0,%1,%2,%3}, {%4,%5,%6,%7}, {%8,%9}, {%0,%1,%2,%3};\n"
        : "+f"(d[0]), "+f"(d[1]), "+f"(d[2]), "+f"(d[3])
        : "r"(a[0]), "r"(a[1]), "r"(a[2]), "r"(a[3]), "r"(b[0]), "r"(b[1]));
}
__device__ __forceinline__ void ldmatrix_x2_trans(uint32_t& r0, uint32_t& r1, uint32_t addr) {
    asm volatile("ldmatrix.sync.aligned.m8n8.x2.trans.shared.b16 {%0,%1}, [%2];"
                 : "=r"(r0), "=r"(r1) : "r"(addr));
}
__device__ __forceinline__ void cp_async16(uint32_t dst_smem, const void* src, int src_bytes) {
    asm volatile("cp.async.cg.shared.global [%0], [%1], 16, %2;"
                 :: "r"(dst_smem), "l"(src), "r"(src_bytes) : "memory");
}
__device__ __forceinline__ void cp_commit() {
    asm volatile("cp.async.commit_group;" ::: "memory");
}
template <int N>
__device__ __forceinline__ void cp_wait() {
    asm volatile("cp.async.wait_group %0;" :: "n"(N) : "memory");
}

// === fused prep: edge convert + degree count + batch convert + zero d_out ===
__global__ void fused_prep_kernel(const void* __restrict__ ei,
                                  const void* __restrict__ batch,
                                  float* __restrict__ outp, int out_n) {
    __shared__ int s_is64;
    if (threadIdx.x == 0) s_is64 = probe_is64((const int*)ei);
    __syncthreads();
    int is64 = s_is64;
    int e = blockIdx.x * blockDim.x + threadIdx.x;
    if (e < NEDGES) {
        int s, d;
        if (is64) {
            const long long* p = (const long long*)ei;
            s = (int)p[e];
            d = (int)p[NEDGES + e];
        } else {
            const int* p = (const int*)ei;
            s = p[e];
            d = p[NEDGES + e];
        }
        s = clampi(s, 0, NNODES - 1);
        d = clampi(d, 0, NNODES - 1);
        g_src[e] = s;
        g_dst[e] = d;
        atomicAdd(&g_cnt[d], 1);
    }
    if (e < NNODES) {
        int g;
        if (is64) g = (int)((const long long*)batch)[e];
        else      g = ((const int*)batch)[e];
        g_batch[e] = clampi(g, 0, NGRAPHS - 1);
    }
    if (e < out_n) outp[e] = 0.f;
}

// === convert x and W0/W1/W2 to fp16 (streaming, 8 floats/thread) ===
__device__ __forceinline__ uint4 pack8(float4 a, float4 b) {
    __half2 h0 = __floats2half2_rn(a.x, a.y);
    __half2 h1 = __floats2half2_rn(a.z, a.w);
    __half2 h2 = __floats2half2_rn(b.x, b.y);
    __half2 h3 = __floats2half2_rn(b.z, b.w);
    uint4 u;
    u.x = *(uint32_t*)&h0; u.y = *(uint32_t*)&h1;
    u.z = *(uint32_t*)&h2; u.w = *(uint32_t*)&h3;
    return u;
}
__global__ void convert_fp16_kernel(const float* __restrict__ x,
                                    const float* __restrict__ W0,
                                    const float* __restrict__ W1,
                                    const float* __restrict__ W2) {
    int idx = blockIdx.x * blockDim.x + threadIdx.x;
    const int NX = NNODES * 128 / 8;   // 800000 threads for x
    if (idx < NX) {
        const float4* xp = (const float4*)x;
        ((uint4*)g_xh)[idx] = pack8(xp[idx * 2], xp[idx * 2 + 1]);
    }
    if (idx < 2048) {                              // W0: 16384 floats
        const float4* p = (const float4*)W0;
        ((uint4*)g_Wh0)[idx] = pack8(p[idx * 2], p[idx * 2 + 1]);
    } else if (idx < 4096) {                       // W1
        int j = idx - 2048;
        const float4* p = (const float4*)W1;
        ((uint4*)g_Wh1)[j] = pack8(p[j * 2], p[j * 2 + 1]);
    } else if (idx < 5120) {                       // W2: 8192 floats
        int j = idx - 4096;
        const float4* p = (const float4*)W2;
        ((uint4*)g_Wh2)[j] = pack8(p[j * 2], p[j * 2 + 1]);
    }
}

// single-block scan; consumes g_cnt and resets it to 0 for the next replay
__global__ void scan_kernel() {
    __shared__ int partial[1024];
    const int tid = threadIdx.x;
    const int CH = (NNODES + 1023) / 1024;  // 49
    int lo = tid * CH;
    int hi = lo + CH;
    if (lo > NNODES) lo = NNODES;
    if (hi > NNODES) hi = NNODES;
    int sum = 0;
    for (int i = lo; i < hi; i++) sum += g_cnt[i];
    partial[tid] = sum;
    __syncthreads();
#pragma unroll
    for (int off = 1; off < 1024; off <<= 1) {
        int t = (tid >= off) ? partial[tid - off] : 0;
        __syncthreads();
        partial[tid] += t;
        __syncthreads();
    }
    int run = partial[tid] - sum;
    for (int i = lo; i < hi; i++) {
        int c = g_cnt[i];
        g_cnt[i] = 0;
        g_off[i] = run;
        g_cur[i] = run;
        run += c;
    }
    if (tid == 0) g_off[NNODES] = NEDGES;
}

__global__ void scatter_kernel() {
    int e = blockIdx.x * blockDim.x + threadIdx.x;
    if (e >= NEDGES) return;
    int pos = atomicAdd(&g_cur[g_dst[e]], 1);
    if (pos >= 0 && pos < NEDGES) g_esrc[pos] = g_src[e];
}

// ===== fp16 HMMA GEMM, cp.async double-buffered, + fused alpha =====
// A: fp16 (g_xh/bufA/bufB, 128 halfs/row). W: fp16 (g_Wh*, K-major BN halfs/row).
template <int BN>
__launch_bounds__(256)
__global__ void gemm_tc_kernel(int insel, const __half* __restrict__ Wh,
                               const float* __restrict__ a_s,
                               const float* __restrict__ a_d) {
    constexpr int BM = 128, BK = 32;
    constexpr int SA = BK + 8;        // A smem stride (halfs); 80B rows
    constexpr int SB = BN + 8;        // B smem stride (halfs), K-major
    constexpr int NT = BN / 16;       // n-tiles per warp (8 or 4)
    constexpr int ASTG = BM * SA;     // halfs per A stage
    constexpr int BSTG = BK * SB;     // halfs per B stage
    constexpr int NKT = 128 / BK;     // 4 k-tiles
    __shared__ __align__(16) __half As[2 * ASTG];
    __shared__ __align__(16) __half Bs[2 * BSTG];
    const int tid = threadIdx.x;
    const int lane = tid & 31, warp = tid >> 5;
    const int g = lane >> 2, tig = lane & 3;
    const int wm = (warp & 3) * 32;
    const int wn = (warp >> 2) * (BN / 2);
    const int blockRow = blockIdx.x * BM;
    const uint32_t as_base = (uint32_t)__cvta_generic_to_shared(As);
    const uint32_t bs_base = (uint32_t)__cvta_generic_to_shared(Bs);
    const uint4* Ap = (const uint4*)sel_in(insel);
    const uint4* Wp = (const uint4*)Wh;

    // ---- async tile loaders ----
    auto load_tiles = [&](int kt, int stage) {
        // A: 4 uint4 per row (32 halfs), 512 uint4 total, 2/thread
#pragma unroll
        for (int i = 0; i < 2; i++) {
            int s = tid + i * 256;
            int r = s >> 2;            // 0..127
            int q = s & 3;
            int row = blockRow + r;
            int ok = (row < NNODES) ? 16 : 0;
            const uint4* src = Ap + ((size_t)(row < NNODES ? row : 0) * 16 + kt * 4 + q);
            cp_async16(as_base + (uint32_t)(stage * ASTG + r * SA + q * 8) * 2, src, ok);
        }
        // B: BN/8 uint4 per row, 32 rows
        constexpr int NU4 = BK * BN / 8;      // 512 (BN=128) or 256 (BN=64)
#pragma unroll
        for (int i = 0; i < NU4 / 256; i++) {
            int s = tid + i * 256;
            int r = s / (BN / 8);
            int q = s % (BN / 8);
            const uint4* src = Wp + ((size_t)(kt * BK + r) * (BN / 8) + q);
            cp_async16(bs_base + (uint32_t)(stage * BSTG + r * SB + q * 8) * 2, src, 16);
        }
        cp_commit();
    };

    float acc[2][NT][4];
#pragma unroll
    for (int mt = 0; mt < 2; mt++)
#pragma unroll
        for (int nt = 0; nt < NT; nt++)
#pragma unroll
            for (int k = 0; k < 4; k++) acc[mt][nt][k] = 0.f;

    load_tiles(0, 0);
#pragma unroll
    for (int kt = 0; kt < NKT; kt++) {
        int stage = kt & 1;
        if (kt + 1 < NKT) {
            load_tiles(kt + 1, (kt + 1) & 1);
            cp_wait<1>();
        } else {
            cp_wait<0>();
        }
        __syncthreads();
        const __half* Ast = As + stage * ASTG;
        uint32_t bstage = bs_base + (uint32_t)(stage * BSTG) * 2;
#pragma unroll
        for (int kk = 0; kk < BK; kk += 16) {
            uint32_t afr[2][4];
#pragma unroll
            for (int mt = 0; mt < 2; mt++) {
                int r0 = wm + mt * 16 + g;
                afr[mt][0] = *(const uint32_t*)&Ast[r0 * SA + kk + 2 * tig];
                afr[mt][1] = *(const uint32_t*)&Ast[(r0 + 8) * SA + kk + 2 * tig];
                afr[mt][2] = *(const uint32_t*)&Ast[r0 * SA + kk + 2 * tig + 8];
                afr[mt][3] = *(const uint32_t*)&Ast[(r0 + 8) * SA + kk + 2 * tig + 8];
            }
            int lrow = kk + (lane & 7) + ((lane >> 3) & 1) * 8;
            uint32_t rowaddr = bstage + (uint32_t)(lrow * SB) * 2;
            uint32_t bfr[NT][2];
#pragma unroll
            for (int nt = 0; nt < NT; nt++) {
                uint32_t addr = rowaddr + (uint32_t)(wn + nt * 8) * 2;
                ldmatrix_x2_trans(bfr[nt][0], bfr[nt][1], addr);
            }
#pragma unroll
            for (int mt = 0; mt < 2; mt++)
#pragma unroll
                for (int nt = 0; nt < NT; nt++)
                    mma_f16(acc[mt][nt], afr[mt], bfr[nt]);
        }
        __syncthreads();
    }

    // ---- epilogue 1: store fp16 feature copy ----
#pragma unroll
    for (int mt = 0; mt < 2; mt++) {
        int r0 = blockRow + wm + mt * 16 + g;
#pragma unroll
        for (int nt = 0; nt < NT; nt++) {
            int c = wn + nt * 8 + 2 * tig;
            if (r0 < NNODES)
                g_hh[((size_t)r0 * BN + c) >> 1] =
                    __floats2half2_rn(acc[mt][nt][0], acc[mt][nt][1]);
            if (r0 + 8 < NNODES)
                g_hh[((size_t)(r0 + 8) * BN + c) >> 1] =
                    __floats2half2_rn(acc[mt][nt][2], acc[mt][nt][3]);
        }
    }

    // ---- epilogue 2: fused alpha ----
    float* sA = (float*)As;            // reuse smem: [0,BM) s, [BM,2BM) d
    if (tid < BM) { sA[tid] = 0.f; sA[BM + tid] = 0.f; }
    __syncthreads();
#pragma unroll
    for (int mt = 0; mt < 2; mt++) {
        int lr = wm + mt * 16 + g;
        float s0 = 0.f, d0 = 0.f, s1 = 0.f, d1 = 0.f;
#pragma unroll
        for (int nt = 0; nt < NT; nt++) {
            int c = wn + nt * 8 + 2 * tig;
            float as0 = __ldg(&a_s[c]), as1 = __ldg(&a_s[c + 1]);
            float ad0 = __ldg(&a_d[c]), ad1 = __ldg(&a_d[c + 1]);
            s0 += acc[mt][nt][0] * as0 + acc[mt][nt][1] * as1;
            d0 += acc[mt][nt][0] * ad0 + acc[mt][nt][1] * ad1;
            s1 += acc[mt][nt][2] * as0 + acc[mt][nt][3] * as1;
            d1 += acc[mt][nt][2] * ad0 + acc[mt][nt][3] * ad1;
        }
        atomicAdd(&sA[lr], s0);      atomicAdd(&sA[BM + lr], d0);
        atomicAdd(&sA[lr + 8], s1);  atomicAdd(&sA[BM + lr + 8], d1);
    }
    __syncthreads();
    if (tid < BM) {
        int row = blockRow + tid;
        if (row < NNODES) {
            g_as[row] = sA[tid];
            g_ad[row] = sA[BM + tid];
        }
    }
}

// == fused softmax + aggregation + bias + relu, single edge pass, warp/node ==
template <int DOUT>
__launch_bounds__(256)
__global__ void gat_agg_kernel(int outsel, const float* __restrict__ bias, int relu) {
    constexpr int VEC = DOUT / 32;
    constexpr int H2 = DOUT / 2;
    int n = (blockIdx.x * blockDim.x + threadIdx.x) >> 5;
    int lane = threadIdx.x & 31;
    if (n >= NNODES) return;
    __half2* __restrict__ out = sel_out(outsel);

    int beg = g_off[n], end = g_off[n + 1];
    float ad_n = g_ad[n];
    float selfe = __expf(lrelu(g_as[n] + ad_n));

    float acc[VEC];
    {
        if constexpr (VEC == 4) {
            uint2 u = *(const uint2*)(g_hh + (size_t)n * H2 + lane * 2);
            float2 v0 = __half22float2(*(__half2*)&u.x);
            float2 v1 = __half22float2(*(__half2*)&u.y);
            acc[0] = selfe * v0.x; acc[1] = selfe * v0.y;
            acc[2] = selfe * v1.x; acc[3] = selfe * v1.y;
        } else {
            float2 v = __half22float2(g_hh[(size_t)n * H2 + lane]);
            acc[0] = selfe * v.x; acc[1] = selfe * v.y;
        }
    }
    float dpart = (lane == 0) ? selfe : 0.f;

    for (int base = beg; base < end; base += 32) {
        int cnt = end - base; if (cnt > 32) cnt = 32;
        int src = 0; float coef = 0.f;
        if (lane < cnt) {
            src = g_esrc[base + lane];
            coef = __expf(lrelu(g_as[src] + ad_n));
        }
        dpart += coef;
        for (int j = 0; j < cnt; j++) {
            int s   = __shfl_sync(0xffffffffu, src, j);
            float c = __shfl_sync(0xffffffffu, coef, j);
            if constexpr (VEC == 4) {
                uint2 u = *(const uint2*)(g_hh + (size_t)s * H2 + lane * 2);
                float2 v0 = __half22float2(*(__half2*)&u.x);
                float2 v1 = __half22float2(*(__half2*)&u.y);
                acc[0] += c * v0.x; acc[1] += c * v0.y;
                acc[2] += c * v1.x; acc[3] += c * v1.y;
            } else {
                float2 v = __half22float2(g_hh[(size_t)s * H2 + lane]);
                acc[0] += c * v.x; acc[1] += c * v.y;
            }
        }
    }

#pragma unroll
    for (int o = 16; o; o >>= 1) dpart += __shfl_xor_sync(0xffffffffu, dpart, o);
    float inv = 1.f / dpart;

    if constexpr (VEC == 4) {
        float4 bv = *(const float4*)(bias + lane * 4);
        float4 w;
        w.x = acc[0] * inv + bv.x; w.y = acc[1] * inv + bv.y;
        w.z = acc[2] * inv + bv.z; w.w = acc[3] * inv + bv.w;
        if (relu) {
            w.x = fmaxf(w.x, 0.f); w.y = fmaxf(w.y, 0.f);
            w.z = fmaxf(w.z, 0.f); w.w = fmaxf(w.w, 0.f);
        }
        __half2 h0 = __floats2half2_rn(w.x, w.y);
        __half2 h1 = __floats2half2_rn(w.z, w.w);
        uint2 st;
        st.x = *(uint32_t*)&h0; st.y = *(uint32_t*)&h1;
        *(uint2*)(out + (size_t)n * 64 + lane * 2) = st;
    } else {
        float2 bv = *(const float2*)(bias + lane * 2);
        float rx = acc[0] * inv + bv.x;
        float ry = acc[1] * inv + bv.y;
        if (relu) { rx = fmaxf(rx, 0.f); ry = fmaxf(ry, 0.f); }
        out[(size_t)n * 32 + lane] = __floats2half2_rn(rx, ry);
    }
}

// ========== global add pool (batch sorted -> run-length accumulate) =========
__global__ void pool_kernel(float* __restrict__ out) {
    const __half* hb = (const __half*)g_bufA;
    int idx = blockIdx.x * blockDim.x + threadIdx.x;
    int grp = idx >> 6;          // node group of 8
    int c = idx & 63;
    int n0 = grp * 8;
    if (n0 >= NNODES) return;
    int ncount = NNODES - n0; if (ncount > 8) ncount = 8;
    int curg = g_batch[n0];
    float acc = 0.f;
    for (int k = 0; k < ncount; k++) {
        int g = g_batch[n0 + k];
        float v = __half2float(hb[(size_t)(n0 + k) * 64 + c]);
        if (g != curg) {
            atomicAdd(out + (size_t)curg * 64 + c, acc);
            acc = 0.f; curg = g;
        }
        acc += v;
    }
    atomicAdd(out + (size_t)curg * 64 + c, acc);
}

// ================= host-side layer driver =================
static void run_layer(int insel, const __half* Wh, const float* av,
                      const float* adv, const float* b, int outsel, int dout, bool relu) {
    int gridm = (NNODES + 127) / 128;
    if (dout == 128)
        gemm_tc_kernel<128><<<gridm, 256>>>(insel, Wh, av, adv);
    else
        gemm_tc_kernel<64><<<gridm, 256>>>(insel, Wh, av, adv);

    int blocks = (NNODES * 32 + 255) / 256;
    if (dout == 128)
        gat_agg_kernel<128><<<blocks, 256>>>(outsel, b, relu ? 1 : 0);
    else
        gat_agg_kernel<64><<<blocks, 256>>>(outsel, b, relu ? 1 : 0);
}

extern "C" void kernel_launch(void* const* d_in, const int* in_sizes, int n_in,
                              void* d_out, int out_size) {
    const float* x = nullptr;
    const void* ei = nullptr;
    const void* batch = nullptr;
    const float* W[3] = {nullptr, nullptr, nullptr};
    const float* v128[6] = {0};
    const float* v64[3]  = {0};
    int wi = 0, n128 = 0, n64 = 0;
    for (int i = 0; i < n_in; i++) {
        int sz = in_sizes[i];
        const void* p = d_in[i];
        if (sz == NNODES * 128)      x = (const float*)p;
        else if (sz == 2 * NEDGES)   ei = p;
        else if (sz == NNODES)       batch = p;
        else if (sz == 128 * 128) { if (wi < 2) W[wi++] = (const float*)p; }
        else if (sz == 128 * 64)     W[2] = (const float*)p;
        else if (sz == 128)        { if (n128 < 6) v128[n128++] = (const float*)p; }
        else if (sz == 64)         { if (n64 < 3)  v64[n64++]  = (const float*)p; }
    }
    float* outp = (float*)d_out;

    __half *Wh0, *Wh1, *Wh2;
    cudaGetSymbolAddress((void**)&Wh0, g_Wh0);
    cudaGetSymbolAddress((void**)&Wh1, g_Wh1);
    cudaGetSymbolAddress((void**)&Wh2, g_Wh2);

    fused_prep_kernel<<<(NEDGES + 255) / 256, 256>>>(ei, batch, outp, out_size);
    convert_fp16_kernel<<<(NNODES * 128 / 8 + 255) / 256, 256>>>(x, W[0], W[1], W[2]);
    scan_kernel<<<1, 1024>>>();
    scatter_kernel<<<(NEDGES + 255) / 256, 256>>>();

    run_layer(3, Wh0, v128[0], v128[1], v128[2], 1, 128, true);   // x -> bufA
    run_layer(1, Wh1, v128[3], v128[4], v128[5], 2, 128, true);   // bufA -> bufB
    run_layer(2, Wh2, v64[0],  v64[1],  v64[2],  1, 64,  false);  // bufB -> bufA

    pool_kernel<<<((NNODES + 7) / 8 * 64 + 255) / 256, 256>>>(outp);
}

// round 16
// speedup vs baseline: 1.0398x; 1.0398x over previous
#include <cuda_runtime.h>
#include <cuda_fp16.h>
#include <cstdint>

#define NNODES 50000
#define NEDGES 800000
#define NGRAPHS 64
#define NEG_SLOPE 0.2f

// ---------------- scratch (static __device__, 16B aligned, no allocation) ---
__device__ __align__(16) __half2 g_xh[(size_t)NNODES * 64];   // x (fp16)
__device__ __align__(16) __half2 g_hh[(size_t)NNODES * 64];   // h (fp16) for gathers
__device__ __align__(16) __half2 g_bufA[(size_t)NNODES * 64]; // layer outputs (fp16)
__device__ __align__(16) __half2 g_bufB[(size_t)NNODES * 64];
__device__ __align__(16) __half g_Wh0[128 * 128];
__device__ __align__(16) __half g_Wh1[128 * 128];
__device__ __align__(16) __half g_Wh2[128 * 64];
__device__ __align__(16) float g_as[NNODES];
__device__ __align__(16) float g_ad[NNODES];
__device__ __align__(16) int g_cnt[NNODES];    // zero at entry; scan resets it
__device__ __align__(16) int g_off[NNODES + 1];
__device__ __align__(16) int g_cur[NNODES];
__device__ __align__(16) int g_esrc[NEDGES];
__device__ __align__(16) int g_src[NEDGES];
__device__ __align__(16) int g_dst[NEDGES];
__device__ __align__(16) int g_batch[NNODES];

__device__ __forceinline__ float lrelu(float x) { return x > 0.f ? x : NEG_SLOPE * x; }
__device__ __forceinline__ int clampi(int v, int lo, int hi) {
    return v < lo ? lo : (v > hi ? hi : v);
}

__device__ __forceinline__ const __half2* sel_in(int i) {
    if (i == 1) return g_bufA;
    if (i == 2) return g_bufB;
    return g_xh;
}
__device__ __forceinline__ __half2* sel_out(int i) {
    if (i == 2) return g_bufB;
    return g_bufA;
}

// int64 little-endian probe: high dword of each elem is 0
__device__ __forceinline__ int probe_is64(const int* ei32) {
    int acc = 0;
#pragma unroll
    for (int i = 1; i < 64; i += 2) acc |= __ldg(&ei32[i]);
    return acc == 0;
}

// ---------------- fp16 mma m16n8k16 + ldmatrix + cp.async ----------------
__device__ __forceinline__ void mma_f16(float* d, const uint32_t* a, const uint32_t* b) {
    asm volatile(
        "mma.sync.aligned.m16n8k16.row.col.f32.f16.f16.f32 "
        "{%0,%1,%2,%3}, {%4,%5,%6,%7}, {%8,%9}, {%0,%1,%2,%3};\n"
        : "+f"(d[0]), "+f"(d[1]), "+f"(d[2]), "+f"(d[3])
        : "r"(a[0]), "r"(a[1]), "r"(a[2]), "r"(a[3]), "r"(b[0]), "r"(b[1]));
}
__device__ __forceinline__ void ldmatrix_x2_trans(uint32_t& r0, uint32_t& r1, uint32_t addr) {
    asm volatile("ldmatrix.sync.aligned.m8n8.x2.trans.shared.b16 {%0,%1}, [%2];"
                 : "=r"(r0), "=r"(r1) : "r"(addr));
}
__device__ __forceinline__ void cp_async16(uint32_t dst_smem, const void* src, int src_bytes) {
    asm volatile("cp.async.cg.shared.global [%0], [%1], 16, %2;"
                 :: "r"(dst_smem), "l"(src), "r"(src_bytes) : "memory");
}
__device__ __forceinline__ void cp_commit() {
    asm volatile("cp.async.commit_group;" ::: "memory");
}
template <int N>
__device__ __forceinline__ void cp_wait() {
    asm volatile("cp.async.wait_group %0;" :: "n"(N) : "memory");
}

// === fused prep: edge convert + degree count + batch convert + zero d_out ===
__global__ void fused_prep_kernel(const void* __restrict__ ei,
                                  const void* __restrict__ batch,
                                  float* __restrict__ outp, int out_n) {
    __shared__ int s_is64;
    if (threadIdx.x == 0) s_is64 = probe_is64((const int*)ei);
    __syncthreads();
    int is64 = s_is64;
    int e = blockIdx.x * blockDim.x + threadIdx.x;
    if (e < NEDGES) {
        int s, d;
        if (is64) {
            const long long* p = (const long long*)ei;
            s = (int)p[e];
            d = (int)p[NEDGES + e];
        } else {
            const int* p = (const int*)ei;
            s = p[e];
            d = p[NEDGES + e];
        }
        s = clampi(s, 0, NNODES - 1);
        d = clampi(d, 0, NNODES - 1);
        g_src[e] = s;
        g_dst[e] = d;
        atomicAdd(&g_cnt[d], 1);
    }
    if (e < NNODES) {
        int g;
        if (is64) g = (int)((const long long*)batch)[e];
        else      g = ((const int*)batch)[e];
        g_batch[e] = clampi(g, 0, NGRAPHS - 1);
    }
    if (e < out_n) outp[e] = 0.f;
}

// === convert x and W0/W1/W2 to fp16 (streaming, 8 floats/thread) ===
__device__ __forceinline__ uint4 pack8(float4 a, float4 b) {
    __half2 h0 = __floats2half2_rn(a.x, a.y);
    __half2 h1 = __floats2half2_rn(a.z, a.w);
    __half2 h2 = __floats2half2_rn(b.x, b.y);
    __half2 h3 = __floats2half2_rn(b.z, b.w);
    uint4 u;
    u.x = *(uint32_t*)&h0; u.y = *(uint32_t*)&h1;
    u.z = *(uint32_t*)&h2; u.w = *(uint32_t*)&h3;
    return u;
}
__global__ void convert_fp16_kernel(const float* __restrict__ x,
                                    const float* __restrict__ W0,
                                    const float* __restrict__ W1,
                                    const float* __restrict__ W2) {
    int idx = blockIdx.x * blockDim.x + threadIdx.x;
    const int NX = NNODES * 128 / 8;   // 800000 threads for x
    if (idx < NX) {
        const float4* xp = (const float4*)x;
        ((uint4*)g_xh)[idx] = pack8(xp[idx * 2], xp[idx * 2 + 1]);
    }
    if (idx < 2048) {                              // W0: 16384 floats
        const float4* p = (const float4*)W0;
        ((uint4*)g_Wh0)[idx] = pack8(p[idx * 2], p[idx * 2 + 1]);
    } else if (idx < 4096) {                       // W1
        int j = idx - 2048;
        const float4* p = (const float4*)W1;
        ((uint4*)g_Wh1)[j] = pack8(p[j * 2], p[j * 2 + 1]);
    } else if (idx < 5120) {                       // W2: 8192 floats
        int j = idx - 4096;
        const float4* p = (const float4*)W2;
        ((uint4*)g_Wh2)[j] = pack8(p[j * 2], p[j * 2 + 1]);
    }
}

// single-block scan; consumes g_cnt and resets it to 0 for the next replay
__global__ void scan_kernel() {
    __shared__ int partial[1024];
    const int tid = threadIdx.x;
    const int CH = (NNODES + 1023) / 1024;  // 49
    int lo = tid * CH;
    int hi = lo + CH;
    if (lo > NNODES) lo = NNODES;
    if (hi > NNODES) hi = NNODES;
    int sum = 0;
    for (int i = lo; i < hi; i++) sum += g_cnt[i];
    partial[tid] = sum;
    __syncthreads();
#pragma unroll
    for (int off = 1; off < 1024; off <<= 1) {
        int t = (tid >= off) ? partial[tid - off] : 0;
        __syncthreads();
        partial[tid] += t;
        __syncthreads();
    }
    int run = partial[tid] - sum;
    for (int i = lo; i < hi; i++) {
        int c = g_cnt[i];
        g_cnt[i] = 0;
        g_off[i] = run;
        g_cur[i] = run;
        run += c;
    }
    if (tid == 0) g_off[NNODES] = NEDGES;
}

__global__ void scatter_kernel() {
    int e = blockIdx.x * blockDim.x + threadIdx.x;
    if (e >= NEDGES) return;
    int pos = atomicAdd(&g_cur[g_dst[e]], 1);
    if (pos >= 0 && pos < NEDGES) g_esrc[pos] = g_src[e];
}

// ===== fp16 HMMA GEMM, cp.async double-buffered, + fused alpha =====
template <int BN>
__launch_bounds__(256)
__global__ void gemm_tc_kernel(int insel, const __half* __restrict__ Wh,
                               const float* __restrict__ a_s,
                               const float* __restrict__ a_d) {
    constexpr int BM = 128, BK = 32;
    constexpr int SA = BK + 8;
    constexpr int SB = BN + 8;
    constexpr int NT = BN / 16;
    constexpr int ASTG = BM * SA;
    constexpr int BSTG = BK * SB;
    constexpr int NKT = 128 / BK;
    __shared__ __align__(16) __half As[2 * ASTG];
    __shared__ __align__(16) __half Bs[2 * BSTG];
    const int tid = threadIdx.x;
    const int lane = tid & 31, warp = tid >> 5;
    const int g = lane >> 2, tig = lane & 3;
    const int wm = (warp & 3) * 32;
    const int wn = (warp >> 2) * (BN / 2);
    const int blockRow = blockIdx.x * BM;
    const uint32_t as_base = (uint32_t)__cvta_generic_to_shared(As);
    const uint32_t bs_base = (uint32_t)__cvta_generic_to_shared(Bs);
    const uint4* Ap = (const uint4*)sel_in(insel);
    const uint4* Wp = (const uint4*)Wh;

    auto load_tiles = [&](int kt, int stage) {
#pragma unroll
        for (int i = 0; i < 2; i++) {
            int s = tid + i * 256;
            int r = s >> 2;
            int q = s & 3;
            int row = blockRow + r;
            int ok = (row < NNODES) ? 16 : 0;
            const uint4* src = Ap + ((size_t)(row < NNODES ? row : 0) * 16 + kt * 4 + q);
            cp_async16(as_base + (uint32_t)(stage * ASTG + r * SA + q * 8) * 2, src, ok);
        }
        constexpr int NU4 = BK * BN / 8;
#pragma unroll
        for (int i = 0; i < NU4 / 256; i++) {
            int s = tid + i * 256;
            int r = s / (BN / 8);
            int q = s % (BN / 8);
            const uint4* src = Wp + ((size_t)(kt * BK + r) * (BN / 8) + q);
            cp_async16(bs_base + (uint32_t)(stage * BSTG + r * SB + q * 8) * 2, src, 16);
        }
        cp_commit();
    };

    float acc[2][NT][4];
#pragma unroll
    for (int mt = 0; mt < 2; mt++)
#pragma unroll
        for (int nt = 0; nt < NT; nt++)
#pragma unroll
            for (int k = 0; k < 4; k++) acc[mt][nt][k] = 0.f;

    load_tiles(0, 0);
#pragma unroll
    for (int kt = 0; kt < NKT; kt++) {
        int stage = kt & 1;
        if (kt + 1 < NKT) {
            load_tiles(kt + 1, (kt + 1) & 1);
            cp_wait<1>();
        } else {
            cp_wait<0>();
        }
        __syncthreads();
        const __half* Ast = As + stage * ASTG;
        uint32_t bstage = bs_base + (uint32_t)(stage * BSTG) * 2;
#pragma unroll
        for (int kk = 0; kk < BK; kk += 16) {
            uint32_t afr[2][4];
#pragma unroll
            for (int mt = 0; mt < 2; mt++) {
                int r0 = wm + mt * 16 + g;
                afr[mt][0] = *(const uint32_t*)&Ast[r0 * SA + kk + 2 * tig];
                afr[mt][1] = *(const uint32_t*)&Ast[(r0 + 8) * SA + kk + 2 * tig];
                afr[mt][2] = *(const uint32_t*)&Ast[r0 * SA + kk + 2 * tig + 8];
                afr[mt][3] = *(const uint32_t*)&Ast[(r0 + 8) * SA + kk + 2 * tig + 8];
            }
            int lrow = kk + (lane & 7) + ((lane >> 3) & 1) * 8;
            uint32_t rowaddr = bstage + (uint32_t)(lrow * SB) * 2;
            uint32_t bfr[NT][2];
#pragma unroll
            for (int nt = 0; nt < NT; nt++) {
                uint32_t addr = rowaddr + (uint32_t)(wn + nt * 8) * 2;
                ldmatrix_x2_trans(bfr[nt][0], bfr[nt][1], addr);
            }
#pragma unroll
            for (int mt = 0; mt < 2; mt++)
#pragma unroll
                for (int nt = 0; nt < NT; nt++)
                    mma_f16(acc[mt][nt], afr[mt], bfr[nt]);
        }
        __syncthreads();
    }

    // ---- epilogue 1: store fp16 feature copy ----
#pragma unroll
    for (int mt = 0; mt < 2; mt++) {
        int r0 = blockRow + wm + mt * 16 + g;
#pragma unroll
        for (int nt = 0; nt < NT; nt++) {
            int c = wn + nt * 8 + 2 * tig;
            if (r0 < NNODES)
                g_hh[((size_t)r0 * BN + c) >> 1] =
                    __floats2half2_rn(acc[mt][nt][0], acc[mt][nt][1]);
            if (r0 + 8 < NNODES)
                g_hh[((size_t)(r0 + 8) * BN + c) >> 1] =
                    __floats2half2_rn(acc[mt][nt][2], acc[mt][nt][3]);
        }
    }

    // ---- epilogue 2: fused alpha ----
    float* sA = (float*)As;
    if (tid < BM) { sA[tid] = 0.f; sA[BM + tid] = 0.f; }
    __syncthreads();
#pragma unroll
    for (int mt = 0; mt < 2; mt++) {
        int lr = wm + mt * 16 + g;
        float s0 = 0.f, d0 = 0.f, s1 = 0.f, d1 = 0.f;
#pragma unroll
        for (int nt = 0; nt < NT; nt++) {
            int c = wn + nt * 8 + 2 * tig;
            float as0 = __ldg(&a_s[c]), as1 = __ldg(&a_s[c + 1]);
            float ad0 = __ldg(&a_d[c]), ad1 = __ldg(&a_d[c + 1]);
            s0 += acc[mt][nt][0] * as0 + acc[mt][nt][1] * as1;
            d0 += acc[mt][nt][0] * ad0 + acc[mt][nt][1] * ad1;
            s1 += acc[mt][nt][2] * as0 + acc[mt][nt][3] * as1;
            d1 += acc[mt][nt][2] * ad0 + acc[mt][nt][3] * ad1;
        }
        atomicAdd(&sA[lr], s0);      atomicAdd(&sA[BM + lr], d0);
        atomicAdd(&sA[lr + 8], s1);  atomicAdd(&sA[BM + lr + 8], d1);
    }
    __syncthreads();
    if (tid < BM) {
        int row = blockRow + tid;
        if (row < NNODES) {
            g_as[row] = sA[tid];
            g_ad[row] = sA[BM + tid];
        }
    }
}

// == fused softmax + aggregation + bias + relu, multi-edge/iter, warp/node ==
// LPE lanes cooperate per edge (uint4 = 8-half gathers); EPI edges in flight.
template <int DOUT>
__launch_bounds__(256)
__global__ void gat_agg_kernel(int outsel, const float* __restrict__ bias, int relu) {
    constexpr int RU4 = DOUT / 8;        // uint4 per feature row (16 or 8)
    constexpr int LPE = RU4;             // lanes per edge (16 or 8)
    constexpr int EPI = 32 / LPE;        // edges per iteration (2 or 4)
    int n = (blockIdx.x * blockDim.x + threadIdx.x) >> 5;
    int lane = threadIdx.x & 31;
    if (n >= NNODES) return;
    __half2* __restrict__ out = sel_out(outsel);
    const uint4* hp = (const uint4*)g_hh;

    int sub = lane & (LPE - 1);          // uint4 index within row
    int grp = lane / LPE;                // edge slot 0..EPI-1

    int beg = g_off[n], end = g_off[n + 1];
    float ad_n = g_ad[n];
    float selfe = __expf(lrelu(g_as[n] + ad_n));

    // acc: 8 channels (sub*8 .. sub*8+7); only grp 0 seeds self-loop
    float acc[8];
    {
        float c0 = (grp == 0) ? selfe : 0.f;
        uint4 u = hp[(size_t)n * RU4 + sub];
        const __half2* h = (const __half2*)&u;
#pragma unroll
        for (int i = 0; i < 4; i++) {
            float2 v = __half22float2(h[i]);
            acc[2 * i] = c0 * v.x;
            acc[2 * i + 1] = c0 * v.y;
        }
    }
    float dpart = (lane == 0) ? selfe : 0.f;

    for (int base = beg; base < end; base += 32) {
        int cnt = end - base; if (cnt > 32) cnt = 32;
        int src = 0; float coef = 0.f;
        if (lane < cnt) {
            src = g_esrc[base + lane];
            coef = __expf(lrelu(g_as[src] + ad_n));
        }
        dpart += coef;
        int iters = (cnt + EPI - 1) / EPI;
        for (int j = 0; j < iters; j++) {
            int eidx = j * EPI + grp;                       // < 32 always
            int s   = __shfl_sync(0xffffffffu, src, eidx);  // 0/0.f if eidx>=cnt
            float c = __shfl_sync(0xffffffffu, coef, eidx);
            uint4 u = hp[(size_t)s * RU4 + sub];
            const __half2* h = (const __half2*)&u;
#pragma unroll
            for (int i = 0; i < 4; i++) {
                float2 v = __half22float2(h[i]);
                acc[2 * i] += c * v.x;
                acc[2 * i + 1] += c * v.y;
            }
        }
    }

    // merge edge-slot partial sums (same channels at lane ^ k*LPE)
#pragma unroll
    for (int o = LPE; o < 32; o <<= 1)
#pragma unroll
        for (int i = 0; i < 8; i++)
            acc[i] += __shfl_xor_sync(0xffffffffu, acc[i], o);

    // denominator across full warp
#pragma unroll
    for (int o = 16; o; o >>= 1) dpart += __shfl_xor_sync(0xffffffffu, dpart, o);
    float inv = 1.f / dpart;

    if (grp == 0) {
        float4 b0 = *(const float4*)(bias + sub * 8);
        float4 b1 = *(const float4*)(bias + sub * 8 + 4);
        float w[8];
        w[0] = acc[0] * inv + b0.x; w[1] = acc[1] * inv + b0.y;
        w[2] = acc[2] * inv + b0.z; w[3] = acc[3] * inv + b0.w;
        w[4] = acc[4] * inv + b1.x; w[5] = acc[5] * inv + b1.y;
        w[6] = acc[6] * inv + b1.z; w[7] = acc[7] * inv + b1.w;
        if (relu) {
#pragma unroll
            for (int i = 0; i < 8; i++) w[i] = fmaxf(w[i], 0.f);
        }
        __half2 h0 = __floats2half2_rn(w[0], w[1]);
        __half2 h1 = __floats2half2_rn(w[2], w[3]);
        __half2 h2 = __floats2half2_rn(w[4], w[5]);
        __half2 h3 = __floats2half2_rn(w[6], w[7]);
        uint4 st;
        st.x = *(uint32_t*)&h0; st.y = *(uint32_t*)&h1;
        st.z = *(uint32_t*)&h2; st.w = *(uint32_t*)&h3;
        ((uint4*)out)[(size_t)n * RU4 + sub] = st;
    }
}

// ========== global add pool (batch sorted -> run-length accumulate) =========
__global__ void pool_kernel(float* __restrict__ out) {
    const __half* hb = (const __half*)g_bufA;
    int idx = blockIdx.x * blockDim.x + threadIdx.x;
    int grp = idx >> 6;          // node group of 8
    int c = idx & 63;
    int n0 = grp * 8;
    if (n0 >= NNODES) return;
    int ncount = NNODES - n0; if (ncount > 8) ncount = 8;
    int curg = g_batch[n0];
    float acc = 0.f;
    for (int k = 0; k < ncount; k++) {
        int g = g_batch[n0 + k];
        float v = __half2float(hb[(size_t)(n0 + k) * 64 + c]);
        if (g != curg) {
            atomicAdd(out + (size_t)curg * 64 + c, acc);
            acc = 0.f; curg = g;
        }
        acc += v;
    }
    atomicAdd(out + (size_t)curg * 64 + c, acc);
}

// ================= host-side layer driver =================
static void run_layer(int insel, const __half* Wh, const float* av,
                      const float* adv, const float* b, int outsel, int dout, bool relu) {
    int gridm = (NNODES + 127) / 128;
    if (dout == 128)
        gemm_tc_kernel<128><<<gridm, 256>>>(insel, Wh, av, adv);
    else
        gemm_tc_kernel<64><<<gridm, 256>>>(insel, Wh, av, adv);

    int blocks = (NNODES * 32 + 255) / 256;
    if (dout == 128)
        gat_agg_kernel<128><<<blocks, 256>>>(outsel, b, relu ? 1 : 0);
    else
        gat_agg_kernel<64><<<blocks, 256>>>(outsel, b, relu ? 1 : 0);
}

extern "C" void kernel_launch(void* const* d_in, const int* in_sizes, int n_in,
                              void* d_out, int out_size) {
    const float* x = nullptr;
    const void* ei = nullptr;
    const void* batch = nullptr;
    const float* W[3] = {nullptr, nullptr, nullptr};
    const float* v128[6] = {0};
    const float* v64[3]  = {0};
    int wi = 0, n128 = 0, n64 = 0;
    for (int i = 0; i < n_in; i++) {
        int sz = in_sizes[i];
        const void* p = d_in[i];
        if (sz == NNODES * 128)      x = (const float*)p;
        else if (sz == 2 * NEDGES)   ei = p;
        else if (sz == NNODES)       batch = p;
        else if (sz == 128 * 128) { if (wi < 2) W[wi++] = (const float*)p; }
        else if (sz == 128 * 64)     W[2] = (const float*)p;
        else if (sz == 128)        { if (n128 < 6) v128[n128++] = (const float*)p; }
        else if (sz == 64)         { if (n64 < 3)  v64[n64++]  = (const float*)p; }
    }
    float* outp = (float*)d_out;

    __half *Wh0, *Wh1, *Wh2;
    cudaGetSymbolAddress((void**)&Wh0, g_Wh0);
    cudaGetSymbolAddress((void**)&Wh1, g_Wh1);
    cudaGetSymbolAddress((void**)&Wh2, g_Wh2);

    fused_prep_kernel<<<(NEDGES + 255) / 256, 256>>>(ei, batch, outp, out_size);
    convert_fp16_kernel<<<(NNODES * 128 / 8 + 255) / 256, 256>>>(x, W[0], W[1], W[2]);
    scan_kernel<<<1, 1024>>>();
    scatter_kernel<<<(NEDGES + 255) / 256, 256>>>();

    run_layer(3, Wh0, v128[0], v128[1], v128[2], 1, 128, true);   // x -> bufA
    run_layer(1, Wh1, v128[3], v128[4], v128[5], 2, 128, true);   // bufA -> bufB
    run_layer(2, Wh2, v64[0],  v64[1],  v64[2],  1, 64,  false);  // bufB -> bufA

    pool_kernel<<<((NNODES + 7) / 8 * 64 + 255) / 256, 256>>>(outp);
}